// round 15
// baseline (speedup 1.0000x reference)
#include <cuda_runtime.h>
#include <cuda_fp16.h>

#define NN 50000
#define EE 600000
#define HH 128
#define MIDD 256

typedef unsigned int u32;
typedef unsigned long long u64;

// ---------------- scratch (device globals) ----------------
__device__ float g_agg[3][NN * HH];    // agg1, agg2, agg3 contiguous

// transposed padded fp16 weight images: [n][k] rows, padded strides
__device__ __align__(16) __half g_W1aT[256 * 136];
__device__ __align__(16) __half g_W2aT[128 * 264];
__device__ __align__(16) __half g_W1bT[256 * 40];
__device__ __align__(16) __half g_W2bT[128 * 264];

// node weight images [128n][136k] fp16
__device__ __align__(16) __half g_nW[8][128 * 136];

// ---------------- helpers ----------------
__device__ __forceinline__ u32 cvta_smem(const void* p) {
    u32 a;
    asm("{ .reg .u64 t; cvta.to.shared.u64 t, %1; cvt.u32.u64 %0, t; }"
        : "=r"(a) : "l"(p));
    return a;
}
__device__ __forceinline__ void ldm4(u32 r[4], u32 addr) {
    asm volatile("ldmatrix.sync.aligned.m8n8.x4.shared.b16 {%0,%1,%2,%3}, [%4];"
        : "=r"(r[0]), "=r"(r[1]), "=r"(r[2]), "=r"(r[3]) : "r"(addr));
}
__device__ __forceinline__ void mma16816(float c[4], const u32 a[4], u32 b0, u32 b1) {
    asm volatile(
        "mma.sync.aligned.m16n8k16.row.col.f32.f16.f16.f32 "
        "{%0,%1,%2,%3}, {%4,%5,%6,%7}, {%8,%9}, {%0,%1,%2,%3};"
        : "+f"(c[0]), "+f"(c[1]), "+f"(c[2]), "+f"(c[3])
        : "r"(a[0]), "r"(a[1]), "r"(a[2]), "r"(a[3]), "r"(b0), "r"(b1));
}
__device__ __forceinline__ u32 pack2(float x, float y) {
    __half2 h = __floats2half2_rn(x, y);
    return *(u32*)&h;
}
__device__ __forceinline__ void red4(float* p, float a, float b, float c, float d) {
    asm volatile("red.global.add.v4.f32 [%0], {%1, %2, %3, %4};"
                 :: "l"(p), "f"(a), "f"(b), "f"(c), "f"(d) : "memory");
}
__device__ __forceinline__ void pf_l2(const void* p) {
    asm volatile("prefetch.global.L2 [%0];" :: "l"(p));
}
__device__ __forceinline__ float4 ldcs4(const float4* p) {
    float4 v;
    asm volatile("ld.global.cs.v4.f32 {%0,%1,%2,%3}, [%4];"
        : "=f"(v.x), "=f"(v.y), "=f"(v.z), "=f"(v.w) : "l"(p));
    return v;
}
#define CPA(dst, src) \
    asm volatile("cp.async.cg.shared.global [%0], [%1], 16;" \
                 :: "r"(dst), "l"(src) : "memory")
#define CPC() asm volatile("cp.async.commit_group;" ::: "memory")
#define CPW() asm volatile("cp.async.wait_group 0;" ::: "memory")

// ============================================================================
// Weight prep + agg zeroing fused: the DRAM-bound zeroing overlaps the
// gather/convert work inside one launch (replaces prep kernel + memset node).
// ============================================================================
__global__ void prep_and_zero(const float* __restrict__ Wf1a,
                              const float* __restrict__ Wf1b,
                              const float* __restrict__ Wf2a,
                              const float* __restrict__ Wf2b,
                              const float* __restrict__ W1_rel,
                              const float* __restrict__ W1_root,
                              const float* __restrict__ W2_rel,
                              const float* __restrict__ W2_root,
                              const float* __restrict__ Wc,
                              const float* __restrict__ Wg1,
                              const float* __restrict__ Wg2)
{
    int tid = blockIdx.x * blockDim.x + threadIdx.x;
    int nt = gridDim.x * blockDim.x;

    // zero g_agg (19.2M floats) with float4 stores, grid-strided
    {
        float4* z = (float4*)g_agg;
        const int n4 = 3 * NN * HH / 4;
        float4 zero = make_float4(0.f, 0.f, 0.f, 0.f);
        for (int i = tid; i < n4; i += nt) z[i] = zero;
    }

    for (int i = tid; i < 256 * 128; i += nt) {
        int n = i >> 7, k = i & 127;
        g_W1aT[n * 136 + k] = __float2half(Wf1a[k * 256 + n]);
    }
    for (int i = tid; i < 128 * 256; i += nt) {
        int n = i >> 8, k = i & 255;
        g_W2aT[n * 264 + k] = __float2half(Wf1b[k * 128 + n]);
        g_W2bT[n * 264 + k] = __float2half(Wf2b[k * 128 + n]);
    }
    for (int i = tid; i < 256 * 32; i += nt) {
        int n = i >> 5, k = i & 31;
        g_W1bT[n * 40 + k] = __float2half(Wf2a[k * 256 + n]);
    }
    for (int i = tid; i < 128 * 128; i += nt) {
        int n = i >> 7, k = i & 127;
        g_nW[0][n * 136 + k] = __float2half(W1_rel[k * 128 + n]);
        g_nW[1][n * 136 + k] = __float2half(W1_root[k * 128 + n]);
        g_nW[2][n * 136 + k] = __float2half(W2_rel[k * 128 + n]);
        g_nW[3][n * 136 + k] = __float2half(W2_root[k * 128 + n]);
        g_nW[4][n * 136 + k] = __float2half(Wc[k * 128 + n]);
        g_nW[5][n * 136 + k] = __float2half(Wc[(k + 128) * 128 + n]);
        g_nW[6][n * 136 + k] = __float2half(Wg1[k * 128 + n]);
        g_nW[7][n * 136 + k] = __float2half(Wg2[k * 128 + n]);
    }
}

// ============================================================================
// Edge MLP via HMMA (R12/R14 — 8 tiles/CTA, 293 CTAs; at the mma.sync floor).
// ============================================================================
#define ETILES 8

template<int DK>
__global__ __launch_bounds__(512, 1) void edge_hmma(
    const float* __restrict__ feat,
    const float* __restrict__ ba, const float* __restrict__ bb,
    const float* __restrict__ x, const int* __restrict__ eidx,
    float* __restrict__ agg,
    const __half* __restrict__ W1T, const __half* __restrict__ W2T)
{
    constexpr int SW1 = DK + 8;
    constexpr int W1SZ = 256 * SW1 * 2;
    constexpr int SW2 = 264;
    constexpr int W2SZ = 128 * SW2 * 2;
    constexpr int SA = DK + 8;
    constexpr int ASZ = 256 * SA * 2;
    constexpr int SF = 136;
    constexpr int OW1 = 0;
    constexpr int OW2 = OW1 + W1SZ;
    constexpr int OA  = OW2 + W2SZ;
    constexpr int OFS = OA + ASZ;
    constexpr int FSZ = (DK == 128) ? 0 : 256 * SF * 2;
    constexpr int OBA = OFS + FSZ;
    constexpr int OBB = OBA + 1024;
    constexpr int OIDX = OBB + 512;
    constexpr int NKT = DK / 16;
    constexpr int DK4 = DK / 4;
    constexpr int LD = DK / 8;

    extern __shared__ unsigned char smraw[];
    const u32 sb = cvta_smem(smraw);
    const int tid = threadIdx.x;
    const int w = tid >> 5, lane = tid & 31;
    float* sBa = (float*)(smraw + OBA);
    float* sBb = (float*)(smraw + OBB);
    int* sIdx = (int*)(smraw + OIDX);

    {
        const uint4* w1 = (const uint4*)W1T;
        const uint4* w2 = (const uint4*)W2T;
        uint4* s1 = (uint4*)(smraw + OW1);
        uint4* s2 = (uint4*)(smraw + OW2);
        for (int i = tid; i < W1SZ / 16; i += 512) s1[i] = w1[i];
        for (int i = tid; i < W2SZ / 16; i += 512) s2[i] = w2[i];
        if (tid < 256) sBa[tid] = ba[tid];
        else if (tid < 384) sBb[tid - 256] = bb[tid - 256];
    }

    u32 pf[2 * LD];
    int pfS = 0, pfD = 0;

    auto load_pf = [&](int t) {
        const int e0 = (blockIdx.x * ETILES + t) * 256;
        #pragma unroll
        for (int j = 0; j < LD; j++) {
            int i = tid + j * 512;
            int e = i / DK4, k4 = i % DK4;
            float4 v = make_float4(0.f, 0.f, 0.f, 0.f);
            if (e0 + e < EE) v = *(const float4*)(feat + (size_t)(e0 + e) * DK + k4 * 4);
            pf[2 * j]     = pack2(v.x, v.y);
            pf[2 * j + 1] = pack2(v.z, v.w);
        }
        if (tid < 256) {
            int e = e0 + tid;
            pfS = (e < EE) ? eidx[e] : 0;
            pfD = (e < EE) ? eidx[EE + e] : 0;
        }
    };
    auto store_pf = [&]() {
        __half* base = (__half*)(smraw + OA);
        #pragma unroll
        for (int j = 0; j < LD; j++) {
            int i = tid + j * 512;
            int e = i / DK4, k4 = i % DK4;
            *(uint2*)(base + e * SA + k4 * 4) = make_uint2(pf[2 * j], pf[2 * j + 1]);
        }
        if (tid < 256) {
            sIdx[tid] = pfS;
            sIdx[256 + tid] = pfD;
        }
    };

    load_pf(0);

    for (int t = 0; t < ETILES; t++) {
        const int e0 = (blockIdx.x * ETILES + t) * 256;
        store_pf();
        __syncthreads();

        const u32 abase = sb + OA;
        u32 a1[NKT][4];
        #pragma unroll
        for (int kt = 0; kt < NKT; kt++)
            ldm4(a1[kt], abase + ((16 * w + (lane & 15)) * SA + kt * 16 + ((lane >> 4) << 3)) * 2);

        if (t + 1 < ETILES) load_pf(t + 1);

        {
            int e = tid >> 1;
            int ch = (tid & 1) * 64;
            if (e0 + e < EE) {
                const float* xp = x + (size_t)sIdx[e] * HH + ch;
                pf_l2(xp);
                pf_l2(xp + 32);
            }
        }

        float acc2[16][4];
        #pragma unroll
        for (int j = 0; j < 16; j++)
            #pragma unroll
            for (int q = 0; q < 4; q++) acc2[j][q] = 0.f;

        #pragma unroll
        for (int nc = 0; nc < 4; nc++) {
            float acc1[8][4];
            #pragma unroll
            for (int j = 0; j < 8; j++)
                #pragma unroll
                for (int q = 0; q < 4; q++) acc1[j][q] = 0.f;

            #pragma unroll
            for (int kt = 0; kt < NKT; kt++) {
                #pragma unroll
                for (int nn = 0; nn < 4; nn++) {
                    u32 b[4];
                    ldm4(b, sb + OW1 + ((nc * 64 + nn * 16 + (lane & 7) + ((lane >> 4) << 3)) * SW1
                                        + kt * 16 + (((lane >> 3) & 1) << 3)) * 2);
                    mma16816(acc1[2 * nn],     a1[kt], b[0], b[1]);
                    mma16816(acc1[2 * nn + 1], a1[kt], b[2], b[3]);
                }
            }
            u32 a2[4][4];
            #pragma unroll
            for (int tt = 0; tt < 4; tt++) {
                int c0 = nc * 64 + tt * 16 + 2 * (lane & 3);
                float b0 = sBa[c0], b1 = sBa[c0 + 1];
                float b8 = sBa[c0 + 8], b9 = sBa[c0 + 9];
                a2[tt][0] = pack2(fmaxf(acc1[2 * tt][0] + b0, 0.f),
                                  fmaxf(acc1[2 * tt][1] + b1, 0.f));
                a2[tt][1] = pack2(fmaxf(acc1[2 * tt][2] + b0, 0.f),
                                  fmaxf(acc1[2 * tt][3] + b1, 0.f));
                a2[tt][2] = pack2(fmaxf(acc1[2 * tt + 1][0] + b8, 0.f),
                                  fmaxf(acc1[2 * tt + 1][1] + b9, 0.f));
                a2[tt][3] = pack2(fmaxf(acc1[2 * tt + 1][2] + b8, 0.f),
                                  fmaxf(acc1[2 * tt + 1][3] + b9, 0.f));
            }
            #pragma unroll
            for (int tt = 0; tt < 4; tt++) {
                #pragma unroll
                for (int nn = 0; nn < 8; nn++) {
                    u32 b[4];
                    ldm4(b, sb + OW2 + ((nn * 16 + (lane & 7) + ((lane >> 4) << 3)) * SW2
                                        + nc * 64 + tt * 16 + (((lane >> 3) & 1) << 3)) * 2);
                    mma16816(acc2[2 * nn],     a2[tt], b[0], b[1]);
                    mma16816(acc2[2 * nn + 1], a2[tt], b[2], b[3]);
                }
            }
        }

        __half* F = (DK == 128) ? (__half*)(smraw + OA) : (__half*)(smraw + OFS);
        {
            int row = 16 * w + (lane >> 2);
            #pragma unroll
            for (int j = 0; j < 16; j++) {
                int col = j * 8 + 2 * (lane & 3);
                *(u32*)(F + row * SF + col)       = pack2(acc2[j][0], acc2[j][1]);
                *(u32*)(F + (row + 8) * SF + col) = pack2(acc2[j][2], acc2[j][3]);
            }
        }
        __syncthreads();

        {
            int e = tid >> 1;
            int ch = (tid & 1) * 64;
            if (e0 + e < EE) {
                int src = sIdx[e], dst = sIdx[256 + e];
                const __half* Fr = F + e * SF + ch;
                const float4* xr = (const float4*)(x + (size_t)src * HH + ch);
                const float4* bbp = (const float4*)(sBb + ch);
                float* ap = agg + (size_t)dst * HH + ch;
                #pragma unroll
                for (int q = 0; q < 16; q++) {
                    float4 xv = __ldg(xr + q);
                    float4 bv = bbp[q];
                    float2 f0 = __half22float2(*(const __half2*)(Fr + q * 4));
                    float2 f1 = __half22float2(*(const __half2*)(Fr + q * 4 + 2));
                    red4(ap + q * 4,
                         (f0.x + bv.x) * xv.x, (f0.y + bv.y) * xv.y,
                         (f1.x + bv.z) * xv.z, (f1.y + bv.w) * xv.w);
                }
            }
        }
        __syncthreads();
    }
}

// ============================================================================
// GINE scatter — 4 edges/warp, MLP=8 (78us measured, occ 82%).
// ============================================================================
__global__ __launch_bounds__(256) void gine_scatter(
    const float* __restrict__ x, const float* __restrict__ ea,
    const int* __restrict__ eidx, float* __restrict__ agg3)
{
    int e0 = blockIdx.x * 32 + (threadIdx.x >> 5) * 4;
    int lane = threadIdx.x & 31;

    int s0 = __ldg(eidx + e0),     s1 = __ldg(eidx + e0 + 1);
    int s2 = __ldg(eidx + e0 + 2), s3 = __ldg(eidx + e0 + 3);
    int d0 = __ldg(eidx + EE + e0),     d1 = __ldg(eidx + EE + e0 + 1);
    int d2 = __ldg(eidx + EE + e0 + 2), d3 = __ldg(eidx + EE + e0 + 3);

    const size_t lo = (size_t)lane * 4;
    float4 a0 = ldcs4((const float4*)(ea + (size_t)(e0 + 0) * HH + lo));
    float4 a1 = ldcs4((const float4*)(ea + (size_t)(e0 + 1) * HH + lo));
    float4 a2 = ldcs4((const float4*)(ea + (size_t)(e0 + 2) * HH + lo));
    float4 a3 = ldcs4((const float4*)(ea + (size_t)(e0 + 3) * HH + lo));
    float4 x0 = __ldg((const float4*)(x + (size_t)s0 * HH + lo));
    float4 x1 = __ldg((const float4*)(x + (size_t)s1 * HH + lo));
    float4 x2 = __ldg((const float4*)(x + (size_t)s2 * HH + lo));
    float4 x3 = __ldg((const float4*)(x + (size_t)s3 * HH + lo));

    red4(agg3 + (size_t)d0 * HH + lo, a0.x + x0.x, a0.y + x0.y, a0.z + x0.z, a0.w + x0.w);
    red4(agg3 + (size_t)d1 * HH + lo, a1.x + x1.x, a1.y + x1.y, a1.z + x1.z, a1.w + x1.w);
    red4(agg3 + (size_t)d2 * HH + lo, a2.x + x2.x, a2.y + x2.y, a2.z + x2.z, a2.w + x2.w);
    red4(agg3 + (size_t)d3 * HH + lo, a3.x + x3.x, a3.y + x3.y, a3.z + x3.z, a3.w + x3.w);
}

// ============================================================================
// Node-level fused via HMMA (R14 best — hC held in registers).
// ============================================================================
#define NOA  0
#define NOW0 34816
#define NOW1 69632
#define NOB  104448
#define NODE_DYN 108032

__global__ __launch_bounds__(256, 1) void node_hmma(
    const float* __restrict__ x,
    const float* __restrict__ b1_rel, const float* __restrict__ b2_rel,
    const float* __restrict__ bc, const float* __restrict__ epsp,
    const float* __restrict__ bg1,
    const float* __restrict__ lng, const float* __restrict__ lnb,
    const float* __restrict__ bg2,
    float* __restrict__ out)
{
    extern __shared__ unsigned char smraw[];
    const u32 sb = cvta_smem(smraw);
    const int tid = threadIdx.x;
    const int w = tid >> 5, lane = tid & 31;
    const int n0 = blockIdx.x * 128;

    float* sB1 = (float*)(smraw + NOB);
    float* sB2 = sB1 + 128;
    float* sBc = sB2 + 128;
    float* sBg1 = sBc + 128;
    float* sLg = sBg1 + 128;
    float* sLb = sLg + 128;
    float* sBg2 = sLb + 128;

    auto stageA = [&](const float* src) {
        for (int i = tid; i < 128 * 32; i += 256) {
            int n = i >> 5, k4 = i & 31;
            int row = n0 + n;
            float4 v = make_float4(0.f, 0.f, 0.f, 0.f);
            if (row < NN) v = *(const float4*)(src + (size_t)row * HH + k4 * 4);
            __half* dst = (__half*)(smraw + NOA) + n * 136 + k4 * 4;
            *(u32*)(dst)     = pack2(v.x, v.y);
            *(u32*)(dst + 2) = pack2(v.z, v.w);
        }
    };
    auto loadW_async = [&](int wi, int buf) {
        const uint4* src = (const uint4*)g_nW[wi];
        u32 dst = sb + (buf ? NOW1 : NOW0);
        for (int i = tid; i < 2176; i += 256) CPA(dst + i * 16, src + i);
        CPC();
    };
    auto ldA = [&](u32 fr[8][4]) {
        #pragma unroll
        for (int kt = 0; kt < 8; kt++)
            ldm4(fr[kt], sb + NOA + ((16 * w + (lane & 15)) * 136 + kt * 16 + ((lane >> 4) << 3)) * 2);
    };
    auto gemmB = [&](const u32 fr[8][4], float acc[16][4], int buf) {
        const u32 wb = sb + (buf ? NOW1 : NOW0);
        #pragma unroll
        for (int kt = 0; kt < 8; kt++) {
            #pragma unroll
            for (int nn = 0; nn < 8; nn++) {
                u32 b[4];
                ldm4(b, wb + ((nn * 16 + (lane & 7) + ((lane >> 4) << 3)) * 136
                              + kt * 16 + (((lane >> 3) & 1) << 3)) * 2);
                mma16816(acc[2 * nn],     fr[kt], b[0], b[1]);
                mma16816(acc[2 * nn + 1], fr[kt], b[2], b[3]);
            }
        }
    };
    auto zacc = [&](float acc[16][4]) {
        #pragma unroll
        for (int j = 0; j < 16; j++)
            #pragma unroll
            for (int q = 0; q < 4; q++) acc[j][q] = 0.f;
    };
    auto repack_relu = [&](const float acc[16][4], const float* bias, u32 fr[8][4]) {
        #pragma unroll
        for (int tt = 0; tt < 8; tt++) {
            int c0 = tt * 16 + 2 * (lane & 3);
            float b0 = bias[c0], b1 = bias[c0 + 1];
            float b8 = bias[c0 + 8], b9 = bias[c0 + 9];
            fr[tt][0] = pack2(fmaxf(acc[2 * tt][0] + b0, 0.f),
                              fmaxf(acc[2 * tt][1] + b1, 0.f));
            fr[tt][1] = pack2(fmaxf(acc[2 * tt][2] + b0, 0.f),
                              fmaxf(acc[2 * tt][3] + b1, 0.f));
            fr[tt][2] = pack2(fmaxf(acc[2 * tt + 1][0] + b8, 0.f),
                              fmaxf(acc[2 * tt + 1][1] + b9, 0.f));
            fr[tt][3] = pack2(fmaxf(acc[2 * tt + 1][2] + b8, 0.f),
                              fmaxf(acc[2 * tt + 1][3] + b9, 0.f));
        }
    };

    stageA(x);
    loadW_async(0, 0);
    if (tid < 128) {
        sB1[tid] = b1_rel[tid]; sB2[tid] = b2_rel[tid]; sBc[tid] = bc[tid];
        sBg1[tid] = bg1[tid]; sLg[tid] = lng[tid]; sLb[tid] = lnb[tid];
        sBg2[tid] = bg2[tid];
    }
    CPW();
    __syncthreads();

    u32 xf[8][4];
    ldA(xf);
    __syncthreads();

    float acc[16][4];
    u32 af[8][4];

    // ---------- h1 ----------
    stageA(g_agg[0]);
    loadW_async(1, 1);
    __syncthreads();
    ldA(af);
    zacc(acc);
    gemmB(af, acc, 0);
    CPW();
    __syncthreads();
    loadW_async(2, 0);
    gemmB(xf, acc, 1);
    u32 h1f[8][4];
    repack_relu(acc, sB1, h1f);
    stageA(g_agg[1]);
    CPW();
    __syncthreads();
    loadW_async(3, 1);

    // ---------- h2 ----------
    ldA(af);
    zacc(acc);
    gemmB(af, acc, 0);
    CPW();
    __syncthreads();
    loadW_async(4, 0);
    gemmB(xf, acc, 1);
    u32 h2f[8][4];
    repack_relu(acc, sB2, h2f);
    CPW();
    __syncthreads();
    loadW_async(5, 1);

    // ---------- h = relu(cat @ Wc + bc) ----------
    zacc(acc);
    gemmB(h1f, acc, 0);
    CPW();
    __syncthreads();
    loadW_async(6, 0);
    gemmB(h2f, acc, 1);
    float hC[16][4];
    #pragma unroll
    for (int j = 0; j < 16; j++) {
        int c = j * 8 + 2 * (lane & 3);
        hC[j][0] = fmaxf(acc[j][0] + sBc[c],     0.f);
        hC[j][1] = fmaxf(acc[j][1] + sBc[c + 1], 0.f);
        hC[j][2] = fmaxf(acc[j][2] + sBc[c],     0.f);
        hC[j][3] = fmaxf(acc[j][3] + sBc[c + 1], 0.f);
    }

    // ---------- g = (1+eps)*x + agg3 ----------
    {
        float epsv = 1.0f + *epsp;
        for (int i = tid; i < 128 * 32; i += 256) {
            int n = i >> 5, k4 = i & 31;
            int row = n0 + n;
            float4 xv = make_float4(0.f, 0.f, 0.f, 0.f);
            float4 av = make_float4(0.f, 0.f, 0.f, 0.f);
            if (row < NN) {
                xv = *(const float4*)(x + (size_t)row * HH + k4 * 4);
                av = *(const float4*)(g_agg[2] + (size_t)row * HH + k4 * 4);
            }
            __half* dst = (__half*)(smraw + NOA) + n * 136 + k4 * 4;
            *(u32*)(dst)     = pack2(xv.x * epsv + av.x, xv.y * epsv + av.y);
            *(u32*)(dst + 2) = pack2(xv.z * epsv + av.z, xv.w * epsv + av.w);
        }
    }
    CPW();
    __syncthreads();
    loadW_async(7, 1);

    // ---------- t = g @ Wg1 + bg1; LN; relu ----------
    ldA(af);
    zacc(acc);
    gemmB(af, acc, 0);

    u32 tf[8][4];
    {
        float sA = 0.f, qA = 0.f, sBv = 0.f, qB = 0.f;
        #pragma unroll
        for (int j = 0; j < 16; j++) {
            int c = j * 8 + 2 * (lane & 3);
            acc[j][0] += sBg1[c];
            acc[j][1] += sBg1[c + 1];
            acc[j][2] += sBg1[c];
            acc[j][3] += sBg1[c + 1];
            sA += acc[j][0] + acc[j][1];
            qA += acc[j][0] * acc[j][0] + acc[j][1] * acc[j][1];
            sBv += acc[j][2] + acc[j][3];
            qB += acc[j][2] * acc[j][2] + acc[j][3] * acc[j][3];
        }
        #pragma unroll
        for (int d = 1; d < 4; d <<= 1) {
            sA  += __shfl_xor_sync(0xffffffffu, sA, d);
            qA  += __shfl_xor_sync(0xffffffffu, qA, d);
            sBv += __shfl_xor_sync(0xffffffffu, sBv, d);
            qB  += __shfl_xor_sync(0xffffffffu, qB, d);
        }
        float mA = sA * (1.f / 128.f);
        float vA = qA * (1.f / 128.f) - mA * mA;
        float rA = rsqrtf(vA + 1e-5f);
        float mB = sBv * (1.f / 128.f);
        float vB = qB * (1.f / 128.f) - mB * mB;
        float rB = rsqrtf(vB + 1e-5f);
        #pragma unroll
        for (int j = 0; j < 16; j++) {
            int c = j * 8 + 2 * (lane & 3);
            float g0 = sLg[c], g1 = sLg[c + 1], l0 = sLb[c], l1 = sLb[c + 1];
            acc[j][0] = fmaxf((acc[j][0] - mA) * rA * g0 + l0, 0.f);
            acc[j][1] = fmaxf((acc[j][1] - mA) * rA * g1 + l1, 0.f);
            acc[j][2] = fmaxf((acc[j][2] - mB) * rB * g0 + l0, 0.f);
            acc[j][3] = fmaxf((acc[j][3] - mB) * rB * g1 + l1, 0.f);
        }
        #pragma unroll
        for (int tt = 0; tt < 8; tt++) {
            tf[tt][0] = pack2(acc[2 * tt][0],     acc[2 * tt][1]);
            tf[tt][1] = pack2(acc[2 * tt][2],     acc[2 * tt][3]);
            tf[tt][2] = pack2(acc[2 * tt + 1][0], acc[2 * tt + 1][1]);
            tf[tt][3] = pack2(acc[2 * tt + 1][2], acc[2 * tt + 1][3]);
        }
    }
    CPW();
    __syncthreads();

    // ---------- h3 = t @ Wg2 + bg2 ; out = h + h3 ----------
    zacc(acc);
    gemmB(tf, acc, 1);
    {
        int r0 = n0 + 16 * w + (lane >> 2);
        int r1 = r0 + 8;
        #pragma unroll
        for (int j = 0; j < 16; j++) {
            int c = j * 8 + 2 * (lane & 3);
            float b0 = sBg2[c], b1 = sBg2[c + 1];
            if (r0 < NN) {
                float2 o = make_float2(hC[j][0] + acc[j][0] + b0,
                                       hC[j][1] + acc[j][1] + b1);
                *(float2*)(out + (size_t)r0 * HH + c) = o;
            }
            if (r1 < NN) {
                float2 o = make_float2(hC[j][2] + acc[j][2] + b0,
                                       hC[j][3] + acc[j][3] + b1);
                *(float2*)(out + (size_t)r1 * HH + c) = o;
            }
        }
    }
}

// ============================================================================
// Launch — serial.
// ============================================================================
extern "C" void kernel_launch(void* const* d_in, const int* in_sizes, int n_in,
                              void* d_out, int out_size)
{
    const float* x        = (const float*)d_in[0];
    const float* feature1 = (const float*)d_in[1];
    const float* feature2 = (const float*)d_in[2];
    const int *pei, *ei;
    const float* ea;
    if (in_sizes[3] == 2 * EE) {
        pei = (const int*)d_in[3]; ei = (const int*)d_in[4];
        ea  = (const float*)d_in[5];
    } else {
        ea  = (const float*)d_in[3];
        pei = (const int*)d_in[4]; ei = (const int*)d_in[5];
    }
    const float* Wf1a   = (const float*)d_in[6];
    const float* bf1a   = (const float*)d_in[7];
    const float* Wf1b   = (const float*)d_in[8];
    const float* bf1b   = (const float*)d_in[9];
    const float* Wf2a   = (const float*)d_in[10];
    const float* bf2a   = (const float*)d_in[11];
    const float* Wf2b   = (const float*)d_in[12];
    const float* bf2b   = (const float*)d_in[13];
    const float* W1_rel = (const float*)d_in[14];
    const float* b1_rel = (const float*)d_in[15];
    const float* W1_root= (const float*)d_in[16];
    const float* W2_rel = (const float*)d_in[17];
    const float* b2_rel = (const float*)d_in[18];
    const float* W2_root= (const float*)d_in[19];
    const float* epsp   = (const float*)d_in[20];
    const float* Wg1    = (const float*)d_in[21];
    const float* bg1    = (const float*)d_in[22];
    const float* lng    = (const float*)d_in[23];
    const float* lnb    = (const float*)d_in[24];
    const float* Wg2    = (const float*)d_in[25];
    const float* bg2    = (const float*)d_in[26];
    const float* Wc     = (const float*)d_in[27];
    const float* bc     = (const float*)d_in[28];
    float* out = (float*)d_out;

    float* aggbase;
    __half *w1a, *w2a, *w1b, *w2b;
    cudaGetSymbolAddress((void**)&aggbase, g_agg);
    cudaGetSymbolAddress((void**)&w1a, g_W1aT);
    cudaGetSymbolAddress((void**)&w2a, g_W2aT);
    cudaGetSymbolAddress((void**)&w1b, g_W1bT);
    cudaGetSymbolAddress((void**)&w2b, g_W2bT);
    float* agg1 = aggbase;
    float* agg2 = aggbase + (size_t)NN * HH;
    float* agg3 = aggbase + (size_t)2 * NN * HH;

    const int DYN128 = 210432;
    const int DYN32  = 181760;
    cudaFuncSetAttribute(edge_hmma<128>,
                         cudaFuncAttributeMaxDynamicSharedMemorySize, DYN128);
    cudaFuncSetAttribute(edge_hmma<32>,
                         cudaFuncAttributeMaxDynamicSharedMemorySize, DYN32);
    cudaFuncSetAttribute(node_hmma,
                         cudaFuncAttributeMaxDynamicSharedMemorySize, NODE_DYN);

    // fused: zero agg scratch + convert all weight images in one launch
    prep_and_zero<<<296, 256>>>(Wf1a, Wf1b, Wf2a, Wf2b,
                                W1_rel, W1_root, W2_rel, W2_root, Wc, Wg1, Wg2);

    // 2344 tiles of 256 edges, 8 per CTA -> 293 CTAs (exactly 2 waves)
    edge_hmma<128><<<293, 512, DYN128>>>(feature1, bf1a, bf1b, x, pei, agg1, w1a, w2a);
    edge_hmma<32><<<293, 512, DYN32>>>(feature2, bf2a, bf2b, x, pei, agg2, w1b, w2b);
    gine_scatter<<<EE / 32, 256>>>(x, ea, ei, agg3);

    node_hmma<<<(NN + 127) / 128, 256, NODE_DYN>>>(
        x, b1_rel, b2_rel, bc, epsp, bg1, lng, lnb, bg2, out);
}

// round 16
// speedup vs baseline: 1.0058x; 1.0058x over previous
#include <cuda_runtime.h>
#include <cuda_fp16.h>

#define NN 50000
#define EE 600000
#define HH 128
#define MIDD 256

typedef unsigned int u32;
typedef unsigned long long u64;

// ---------------- scratch (device globals) ----------------
__device__ float g_agg[3][NN * HH];    // agg1, agg2, agg3 contiguous

// transposed padded fp16 weight images: [n][k] rows, padded strides
__device__ __align__(16) __half g_W1aT[256 * 136];
__device__ __align__(16) __half g_W2aT[128 * 264];
__device__ __align__(16) __half g_W1bT[256 * 40];
__device__ __align__(16) __half g_W2bT[128 * 264];

// node weight images [128n][136k] fp16
__device__ __align__(16) __half g_nW[8][128 * 136];

// ---------------- helpers ----------------
__device__ __forceinline__ u32 cvta_smem(const void* p) {
    u32 a;
    asm("{ .reg .u64 t; cvta.to.shared.u64 t, %1; cvt.u32.u64 %0, t; }"
        : "=r"(a) : "l"(p));
    return a;
}
__device__ __forceinline__ void ldm4(u32 r[4], u32 addr) {
    asm volatile("ldmatrix.sync.aligned.m8n8.x4.shared.b16 {%0,%1,%2,%3}, [%4];"
        : "=r"(r[0]), "=r"(r[1]), "=r"(r[2]), "=r"(r[3]) : "r"(addr));
}
__device__ __forceinline__ void mma16816(float c[4], const u32 a[4], u32 b0, u32 b1) {
    asm volatile(
        "mma.sync.aligned.m16n8k16.row.col.f32.f16.f16.f32 "
        "{%0,%1,%2,%3}, {%4,%5,%6,%7}, {%8,%9}, {%0,%1,%2,%3};"
        : "+f"(c[0]), "+f"(c[1]), "+f"(c[2]), "+f"(c[3])
        : "r"(a[0]), "r"(a[1]), "r"(a[2]), "r"(a[3]), "r"(b0), "r"(b1));
}
__device__ __forceinline__ u32 pack2(float x, float y) {
    __half2 h = __floats2half2_rn(x, y);
    return *(u32*)&h;
}
__device__ __forceinline__ void red4(float* p, float a, float b, float c, float d) {
    asm volatile("red.global.add.v4.f32 [%0], {%1, %2, %3, %4};"
                 :: "l"(p), "f"(a), "f"(b), "f"(c), "f"(d) : "memory");
}
__device__ __forceinline__ void pf_l2(const void* p) {
    asm volatile("prefetch.global.L2 [%0];" :: "l"(p));
}
__device__ __forceinline__ float4 ldcs4(const float4* p) {
    float4 v;
    asm volatile("ld.global.cs.v4.f32 {%0,%1,%2,%3}, [%4];"
        : "=f"(v.x), "=f"(v.y), "=f"(v.z), "=f"(v.w) : "l"(p));
    return v;
}
#define CPA(dst, src) \
    asm volatile("cp.async.cg.shared.global [%0], [%1], 16;" \
                 :: "r"(dst), "l"(src) : "memory")
#define CPC() asm volatile("cp.async.commit_group;" ::: "memory")
#define CPW() asm volatile("cp.async.wait_group 0;" ::: "memory")

// ============================================================================
// Weight prep (separate kernel; memset done via cudaMemsetAsync — R14 config).
// ============================================================================
__global__ void prep_weights(const float* __restrict__ Wf1a,
                             const float* __restrict__ Wf1b,
                             const float* __restrict__ Wf2a,
                             const float* __restrict__ Wf2b,
                             const float* __restrict__ W1_rel,
                             const float* __restrict__ W1_root,
                             const float* __restrict__ W2_rel,
                             const float* __restrict__ W2_root,
                             const float* __restrict__ Wc,
                             const float* __restrict__ Wg1,
                             const float* __restrict__ Wg2)
{
    int tid = blockIdx.x * blockDim.x + threadIdx.x;
    int nt = gridDim.x * blockDim.x;
    for (int i = tid; i < 256 * 128; i += nt) {
        int n = i >> 7, k = i & 127;
        g_W1aT[n * 136 + k] = __float2half(Wf1a[k * 256 + n]);
    }
    for (int i = tid; i < 128 * 256; i += nt) {
        int n = i >> 8, k = i & 255;
        g_W2aT[n * 264 + k] = __float2half(Wf1b[k * 128 + n]);
        g_W2bT[n * 264 + k] = __float2half(Wf2b[k * 128 + n]);
    }
    for (int i = tid; i < 256 * 32; i += nt) {
        int n = i >> 5, k = i & 31;
        g_W1bT[n * 40 + k] = __float2half(Wf2a[k * 256 + n]);
    }
    for (int i = tid; i < 128 * 128; i += nt) {
        int n = i >> 7, k = i & 127;
        g_nW[0][n * 136 + k] = __float2half(W1_rel[k * 128 + n]);
        g_nW[1][n * 136 + k] = __float2half(W1_root[k * 128 + n]);
        g_nW[2][n * 136 + k] = __float2half(W2_rel[k * 128 + n]);
        g_nW[3][n * 136 + k] = __float2half(W2_root[k * 128 + n]);
        g_nW[4][n * 136 + k] = __float2half(Wc[k * 128 + n]);
        g_nW[5][n * 136 + k] = __float2half(Wc[(k + 128) * 128 + n]);
        g_nW[6][n * 136 + k] = __float2half(Wg1[k * 128 + n]);
        g_nW[7][n * 136 + k] = __float2half(Wg2[k * 128 + n]);
    }
}

// ============================================================================
// Edge MLP via HMMA (R14 best — 8 tiles/CTA, 293 CTAs; at the mma.sync floor).
// ============================================================================
#define ETILES 8

template<int DK>
__global__ __launch_bounds__(512, 1) void edge_hmma(
    const float* __restrict__ feat,
    const float* __restrict__ ba, const float* __restrict__ bb,
    const float* __restrict__ x, const int* __restrict__ eidx,
    float* __restrict__ agg,
    const __half* __restrict__ W1T, const __half* __restrict__ W2T)
{
    constexpr int SW1 = DK + 8;
    constexpr int W1SZ = 256 * SW1 * 2;
    constexpr int SW2 = 264;
    constexpr int W2SZ = 128 * SW2 * 2;
    constexpr int SA = DK + 8;
    constexpr int ASZ = 256 * SA * 2;
    constexpr int SF = 136;
    constexpr int OW1 = 0;
    constexpr int OW2 = OW1 + W1SZ;
    constexpr int OA  = OW2 + W2SZ;
    constexpr int OFS = OA + ASZ;
    constexpr int FSZ = (DK == 128) ? 0 : 256 * SF * 2;
    constexpr int OBA = OFS + FSZ;
    constexpr int OBB = OBA + 1024;
    constexpr int OIDX = OBB + 512;
    constexpr int NKT = DK / 16;
    constexpr int DK4 = DK / 4;
    constexpr int LD = DK / 8;

    extern __shared__ unsigned char smraw[];
    const u32 sb = cvta_smem(smraw);
    const int tid = threadIdx.x;
    const int w = tid >> 5, lane = tid & 31;
    float* sBa = (float*)(smraw + OBA);
    float* sBb = (float*)(smraw + OBB);
    int* sIdx = (int*)(smraw + OIDX);

    {
        const uint4* w1 = (const uint4*)W1T;
        const uint4* w2 = (const uint4*)W2T;
        uint4* s1 = (uint4*)(smraw + OW1);
        uint4* s2 = (uint4*)(smraw + OW2);
        for (int i = tid; i < W1SZ / 16; i += 512) s1[i] = w1[i];
        for (int i = tid; i < W2SZ / 16; i += 512) s2[i] = w2[i];
        if (tid < 256) sBa[tid] = ba[tid];
        else if (tid < 384) sBb[tid - 256] = bb[tid - 256];
    }

    u32 pf[2 * LD];
    int pfS = 0, pfD = 0;

    auto load_pf = [&](int t) {
        const int e0 = (blockIdx.x * ETILES + t) * 256;
        #pragma unroll
        for (int j = 0; j < LD; j++) {
            int i = tid + j * 512;
            int e = i / DK4, k4 = i % DK4;
            float4 v = make_float4(0.f, 0.f, 0.f, 0.f);
            if (e0 + e < EE) v = *(const float4*)(feat + (size_t)(e0 + e) * DK + k4 * 4);
            pf[2 * j]     = pack2(v.x, v.y);
            pf[2 * j + 1] = pack2(v.z, v.w);
        }
        if (tid < 256) {
            int e = e0 + tid;
            pfS = (e < EE) ? eidx[e] : 0;
            pfD = (e < EE) ? eidx[EE + e] : 0;
        }
    };
    auto store_pf = [&]() {
        __half* base = (__half*)(smraw + OA);
        #pragma unroll
        for (int j = 0; j < LD; j++) {
            int i = tid + j * 512;
            int e = i / DK4, k4 = i % DK4;
            *(uint2*)(base + e * SA + k4 * 4) = make_uint2(pf[2 * j], pf[2 * j + 1]);
        }
        if (tid < 256) {
            sIdx[tid] = pfS;
            sIdx[256 + tid] = pfD;
        }
    };

    load_pf(0);

    for (int t = 0; t < ETILES; t++) {
        const int e0 = (blockIdx.x * ETILES + t) * 256;
        store_pf();
        __syncthreads();

        const u32 abase = sb + OA;
        u32 a1[NKT][4];
        #pragma unroll
        for (int kt = 0; kt < NKT; kt++)
            ldm4(a1[kt], abase + ((16 * w + (lane & 15)) * SA + kt * 16 + ((lane >> 4) << 3)) * 2);

        if (t + 1 < ETILES) load_pf(t + 1);

        {
            int e = tid >> 1;
            int ch = (tid & 1) * 64;
            if (e0 + e < EE) {
                const float* xp = x + (size_t)sIdx[e] * HH + ch;
                pf_l2(xp);
                pf_l2(xp + 32);
            }
        }

        float acc2[16][4];
        #pragma unroll
        for (int j = 0; j < 16; j++)
            #pragma unroll
            for (int q = 0; q < 4; q++) acc2[j][q] = 0.f;

        #pragma unroll
        for (int nc = 0; nc < 4; nc++) {
            float acc1[8][4];
            #pragma unroll
            for (int j = 0; j < 8; j++)
                #pragma unroll
                for (int q = 0; q < 4; q++) acc1[j][q] = 0.f;

            #pragma unroll
            for (int kt = 0; kt < NKT; kt++) {
                #pragma unroll
                for (int nn = 0; nn < 4; nn++) {
                    u32 b[4];
                    ldm4(b, sb + OW1 + ((nc * 64 + nn * 16 + (lane & 7) + ((lane >> 4) << 3)) * SW1
                                        + kt * 16 + (((lane >> 3) & 1) << 3)) * 2);
                    mma16816(acc1[2 * nn],     a1[kt], b[0], b[1]);
                    mma16816(acc1[2 * nn + 1], a1[kt], b[2], b[3]);
                }
            }
            u32 a2[4][4];
            #pragma unroll
            for (int tt = 0; tt < 4; tt++) {
                int c0 = nc * 64 + tt * 16 + 2 * (lane & 3);
                float b0 = sBa[c0], b1 = sBa[c0 + 1];
                float b8 = sBa[c0 + 8], b9 = sBa[c0 + 9];
                a2[tt][0] = pack2(fmaxf(acc1[2 * tt][0] + b0, 0.f),
                                  fmaxf(acc1[2 * tt][1] + b1, 0.f));
                a2[tt][1] = pack2(fmaxf(acc1[2 * tt][2] + b0, 0.f),
                                  fmaxf(acc1[2 * tt][3] + b1, 0.f));
                a2[tt][2] = pack2(fmaxf(acc1[2 * tt + 1][0] + b8, 0.f),
                                  fmaxf(acc1[2 * tt + 1][1] + b9, 0.f));
                a2[tt][3] = pack2(fmaxf(acc1[2 * tt + 1][2] + b8, 0.f),
                                  fmaxf(acc1[2 * tt + 1][3] + b9, 0.f));
            }
            #pragma unroll
            for (int tt = 0; tt < 4; tt++) {
                #pragma unroll
                for (int nn = 0; nn < 8; nn++) {
                    u32 b[4];
                    ldm4(b, sb + OW2 + ((nn * 16 + (lane & 7) + ((lane >> 4) << 3)) * SW2
                                        + nc * 64 + tt * 16 + (((lane >> 3) & 1) << 3)) * 2);
                    mma16816(acc2[2 * nn],     a2[tt], b[0], b[1]);
                    mma16816(acc2[2 * nn + 1], a2[tt], b[2], b[3]);
                }
            }
        }

        __half* F = (DK == 128) ? (__half*)(smraw + OA) : (__half*)(smraw + OFS);
        {
            int row = 16 * w + (lane >> 2);
            #pragma unroll
            for (int j = 0; j < 16; j++) {
                int col = j * 8 + 2 * (lane & 3);
                *(u32*)(F + row * SF + col)       = pack2(acc2[j][0], acc2[j][1]);
                *(u32*)(F + (row + 8) * SF + col) = pack2(acc2[j][2], acc2[j][3]);
            }
        }
        __syncthreads();

        {
            int e = tid >> 1;
            int ch = (tid & 1) * 64;
            if (e0 + e < EE) {
                int src = sIdx[e], dst = sIdx[256 + e];
                const __half* Fr = F + e * SF + ch;
                const float4* xr = (const float4*)(x + (size_t)src * HH + ch);
                const float4* bbp = (const float4*)(sBb + ch);
                float* ap = agg + (size_t)dst * HH + ch;
                #pragma unroll
                for (int q = 0; q < 16; q++) {
                    float4 xv = __ldg(xr + q);
                    float4 bv = bbp[q];
                    float2 f0 = __half22float2(*(const __half2*)(Fr + q * 4));
                    float2 f1 = __half22float2(*(const __half2*)(Fr + q * 4 + 2));
                    red4(ap + q * 4,
                         (f0.x + bv.x) * xv.x, (f0.y + bv.y) * xv.y,
                         (f1.x + bv.z) * xv.z, (f1.y + bv.w) * xv.w);
                }
            }
        }
        __syncthreads();
    }
}

// ============================================================================
// GINE scatter — 4 edges/warp, MLP=8 (78us measured, occ 82%).
// ============================================================================
__global__ __launch_bounds__(256) void gine_scatter(
    const float* __restrict__ x, const float* __restrict__ ea,
    const int* __restrict__ eidx, float* __restrict__ agg3)
{
    int e0 = blockIdx.x * 32 + (threadIdx.x >> 5) * 4;
    int lane = threadIdx.x & 31;

    int s0 = __ldg(eidx + e0),     s1 = __ldg(eidx + e0 + 1);
    int s2 = __ldg(eidx + e0 + 2), s3 = __ldg(eidx + e0 + 3);
    int d0 = __ldg(eidx + EE + e0),     d1 = __ldg(eidx + EE + e0 + 1);
    int d2 = __ldg(eidx + EE + e0 + 2), d3 = __ldg(eidx + EE + e0 + 3);

    const size_t lo = (size_t)lane * 4;
    float4 a0 = ldcs4((const float4*)(ea + (size_t)(e0 + 0) * HH + lo));
    float4 a1 = ldcs4((const float4*)(ea + (size_t)(e0 + 1) * HH + lo));
    float4 a2 = ldcs4((const float4*)(ea + (size_t)(e0 + 2) * HH + lo));
    float4 a3 = ldcs4((const float4*)(ea + (size_t)(e0 + 3) * HH + lo));
    float4 x0 = __ldg((const float4*)(x + (size_t)s0 * HH + lo));
    float4 x1 = __ldg((const float4*)(x + (size_t)s1 * HH + lo));
    float4 x2 = __ldg((const float4*)(x + (size_t)s2 * HH + lo));
    float4 x3 = __ldg((const float4*)(x + (size_t)s3 * HH + lo));

    red4(agg3 + (size_t)d0 * HH + lo, a0.x + x0.x, a0.y + x0.y, a0.z + x0.z, a0.w + x0.w);
    red4(agg3 + (size_t)d1 * HH + lo, a1.x + x1.x, a1.y + x1.y, a1.z + x1.z, a1.w + x1.w);
    red4(agg3 + (size_t)d2 * HH + lo, a2.x + x2.x, a2.y + x2.y, a2.z + x2.z, a2.w + x2.w);
    red4(agg3 + (size_t)d3 * HH + lo, a3.x + x3.x, a3.y + x3.y, a3.z + x3.z, a3.w + x3.w);
}

// ============================================================================
// Node-level fused via HMMA (R14 best — hC held in registers).
// ============================================================================
#define NOA  0
#define NOW0 34816
#define NOW1 69632
#define NOB  104448
#define NODE_DYN 108032

__global__ __launch_bounds__(256, 1) void node_hmma(
    const float* __restrict__ x,
    const float* __restrict__ b1_rel, const float* __restrict__ b2_rel,
    const float* __restrict__ bc, const float* __restrict__ epsp,
    const float* __restrict__ bg1,
    const float* __restrict__ lng, const float* __restrict__ lnb,
    const float* __restrict__ bg2,
    float* __restrict__ out)
{
    extern __shared__ unsigned char smraw[];
    const u32 sb = cvta_smem(smraw);
    const int tid = threadIdx.x;
    const int w = tid >> 5, lane = tid & 31;
    const int n0 = blockIdx.x * 128;

    float* sB1 = (float*)(smraw + NOB);
    float* sB2 = sB1 + 128;
    float* sBc = sB2 + 128;
    float* sBg1 = sBc + 128;
    float* sLg = sBg1 + 128;
    float* sLb = sLg + 128;
    float* sBg2 = sLb + 128;

    auto stageA = [&](const float* src) {
        for (int i = tid; i < 128 * 32; i += 256) {
            int n = i >> 5, k4 = i & 31;
            int row = n0 + n;
            float4 v = make_float4(0.f, 0.f, 0.f, 0.f);
            if (row < NN) v = *(const float4*)(src + (size_t)row * HH + k4 * 4);
            __half* dst = (__half*)(smraw + NOA) + n * 136 + k4 * 4;
            *(u32*)(dst)     = pack2(v.x, v.y);
            *(u32*)(dst + 2) = pack2(v.z, v.w);
        }
    };
    auto loadW_async = [&](int wi, int buf) {
        const uint4* src = (const uint4*)g_nW[wi];
        u32 dst = sb + (buf ? NOW1 : NOW0);
        for (int i = tid; i < 2176; i += 256) CPA(dst + i * 16, src + i);
        CPC();
    };
    auto ldA = [&](u32 fr[8][4]) {
        #pragma unroll
        for (int kt = 0; kt < 8; kt++)
            ldm4(fr[kt], sb + NOA + ((16 * w + (lane & 15)) * 136 + kt * 16 + ((lane >> 4) << 3)) * 2);
    };
    auto gemmB = [&](const u32 fr[8][4], float acc[16][4], int buf) {
        const u32 wb = sb + (buf ? NOW1 : NOW0);
        #pragma unroll
        for (int kt = 0; kt < 8; kt++) {
            #pragma unroll
            for (int nn = 0; nn < 8; nn++) {
                u32 b[4];
                ldm4(b, wb + ((nn * 16 + (lane & 7) + ((lane >> 4) << 3)) * 136
                              + kt * 16 + (((lane >> 3) & 1) << 3)) * 2);
                mma16816(acc[2 * nn],     fr[kt], b[0], b[1]);
                mma16816(acc[2 * nn + 1], fr[kt], b[2], b[3]);
            }
        }
    };
    auto zacc = [&](float acc[16][4]) {
        #pragma unroll
        for (int j = 0; j < 16; j++)
            #pragma unroll
            for (int q = 0; q < 4; q++) acc[j][q] = 0.f;
    };
    auto repack_relu = [&](const float acc[16][4], const float* bias, u32 fr[8][4]) {
        #pragma unroll
        for (int tt = 0; tt < 8; tt++) {
            int c0 = tt * 16 + 2 * (lane & 3);
            float b0 = bias[c0], b1 = bias[c0 + 1];
            float b8 = bias[c0 + 8], b9 = bias[c0 + 9];
            fr[tt][0] = pack2(fmaxf(acc[2 * tt][0] + b0, 0.f),
                              fmaxf(acc[2 * tt][1] + b1, 0.f));
            fr[tt][1] = pack2(fmaxf(acc[2 * tt][2] + b0, 0.f),
                              fmaxf(acc[2 * tt][3] + b1, 0.f));
            fr[tt][2] = pack2(fmaxf(acc[2 * tt + 1][0] + b8, 0.f),
                              fmaxf(acc[2 * tt + 1][1] + b9, 0.f));
            fr[tt][3] = pack2(fmaxf(acc[2 * tt + 1][2] + b8, 0.f),
                              fmaxf(acc[2 * tt + 1][3] + b9, 0.f));
        }
    };

    stageA(x);
    loadW_async(0, 0);
    if (tid < 128) {
        sB1[tid] = b1_rel[tid]; sB2[tid] = b2_rel[tid]; sBc[tid] = bc[tid];
        sBg1[tid] = bg1[tid]; sLg[tid] = lng[tid]; sLb[tid] = lnb[tid];
        sBg2[tid] = bg2[tid];
    }
    CPW();
    __syncthreads();

    u32 xf[8][4];
    ldA(xf);
    __syncthreads();

    float acc[16][4];
    u32 af[8][4];

    // ---------- h1 ----------
    stageA(g_agg[0]);
    loadW_async(1, 1);
    __syncthreads();
    ldA(af);
    zacc(acc);
    gemmB(af, acc, 0);
    CPW();
    __syncthreads();
    loadW_async(2, 0);
    gemmB(xf, acc, 1);
    u32 h1f[8][4];
    repack_relu(acc, sB1, h1f);
    stageA(g_agg[1]);
    CPW();
    __syncthreads();
    loadW_async(3, 1);

    // ---------- h2 ----------
    ldA(af);
    zacc(acc);
    gemmB(af, acc, 0);
    CPW();
    __syncthreads();
    loadW_async(4, 0);
    gemmB(xf, acc, 1);
    u32 h2f[8][4];
    repack_relu(acc, sB2, h2f);
    CPW();
    __syncthreads();
    loadW_async(5, 1);

    // ---------- h = relu(cat @ Wc + bc) ----------
    zacc(acc);
    gemmB(h1f, acc, 0);
    CPW();
    __syncthreads();
    loadW_async(6, 0);
    gemmB(h2f, acc, 1);
    float hC[16][4];
    #pragma unroll
    for (int j = 0; j < 16; j++) {
        int c = j * 8 + 2 * (lane & 3);
        hC[j][0] = fmaxf(acc[j][0] + sBc[c],     0.f);
        hC[j][1] = fmaxf(acc[j][1] + sBc[c + 1], 0.f);
        hC[j][2] = fmaxf(acc[j][2] + sBc[c],     0.f);
        hC[j][3] = fmaxf(acc[j][3] + sBc[c + 1], 0.f);
    }

    // ---------- g = (1+eps)*x + agg3 ----------
    {
        float epsv = 1.0f + *epsp;
        for (int i = tid; i < 128 * 32; i += 256) {
            int n = i >> 5, k4 = i & 31;
            int row = n0 + n;
            float4 xv = make_float4(0.f, 0.f, 0.f, 0.f);
            float4 av = make_float4(0.f, 0.f, 0.f, 0.f);
            if (row < NN) {
                xv = *(const float4*)(x + (size_t)row * HH + k4 * 4);
                av = *(const float4*)(g_agg[2] + (size_t)row * HH + k4 * 4);
            }
            __half* dst = (__half*)(smraw + NOA) + n * 136 + k4 * 4;
            *(u32*)(dst)     = pack2(xv.x * epsv + av.x, xv.y * epsv + av.y);
            *(u32*)(dst + 2) = pack2(xv.z * epsv + av.z, xv.w * epsv + av.w);
        }
    }
    CPW();
    __syncthreads();
    loadW_async(7, 1);

    // ---------- t = g @ Wg1 + bg1; LN; relu ----------
    ldA(af);
    zacc(acc);
    gemmB(af, acc, 0);

    u32 tf[8][4];
    {
        float sA = 0.f, qA = 0.f, sBv = 0.f, qB = 0.f;
        #pragma unroll
        for (int j = 0; j < 16; j++) {
            int c = j * 8 + 2 * (lane & 3);
            acc[j][0] += sBg1[c];
            acc[j][1] += sBg1[c + 1];
            acc[j][2] += sBg1[c];
            acc[j][3] += sBg1[c + 1];
            sA += acc[j][0] + acc[j][1];
            qA += acc[j][0] * acc[j][0] + acc[j][1] * acc[j][1];
            sBv += acc[j][2] + acc[j][3];
            qB += acc[j][2] * acc[j][2] + acc[j][3] * acc[j][3];
        }
        #pragma unroll
        for (int d = 1; d < 4; d <<= 1) {
            sA  += __shfl_xor_sync(0xffffffffu, sA, d);
            qA  += __shfl_xor_sync(0xffffffffu, qA, d);
            sBv += __shfl_xor_sync(0xffffffffu, sBv, d);
            qB  += __shfl_xor_sync(0xffffffffu, qB, d);
        }
        float mA = sA * (1.f / 128.f);
        float vA = qA * (1.f / 128.f) - mA * mA;
        float rA = rsqrtf(vA + 1e-5f);
        float mB = sBv * (1.f / 128.f);
        float vB = qB * (1.f / 128.f) - mB * mB;
        float rB = rsqrtf(vB + 1e-5f);
        #pragma unroll
        for (int j = 0; j < 16; j++) {
            int c = j * 8 + 2 * (lane & 3);
            float g0 = sLg[c], g1 = sLg[c + 1], l0 = sLb[c], l1 = sLb[c + 1];
            acc[j][0] = fmaxf((acc[j][0] - mA) * rA * g0 + l0, 0.f);
            acc[j][1] = fmaxf((acc[j][1] - mA) * rA * g1 + l1, 0.f);
            acc[j][2] = fmaxf((acc[j][2] - mB) * rB * g0 + l0, 0.f);
            acc[j][3] = fmaxf((acc[j][3] - mB) * rB * g1 + l1, 0.f);
        }
        #pragma unroll
        for (int tt = 0; tt < 8; tt++) {
            tf[tt][0] = pack2(acc[2 * tt][0],     acc[2 * tt][1]);
            tf[tt][1] = pack2(acc[2 * tt][2],     acc[2 * tt][3]);
            tf[tt][2] = pack2(acc[2 * tt + 1][0], acc[2 * tt + 1][1]);
            tf[tt][3] = pack2(acc[2 * tt + 1][2], acc[2 * tt + 1][3]);
        }
    }
    CPW();
    __syncthreads();

    // ---------- h3 = t @ Wg2 + bg2 ; out = h + h3 ----------
    zacc(acc);
    gemmB(tf, acc, 1);
    {
        int r0 = n0 + 16 * w + (lane >> 2);
        int r1 = r0 + 8;
        #pragma unroll
        for (int j = 0; j < 16; j++) {
            int c = j * 8 + 2 * (lane & 3);
            float b0 = sBg2[c], b1 = sBg2[c + 1];
            if (r0 < NN) {
                float2 o = make_float2(hC[j][0] + acc[j][0] + b0,
                                       hC[j][1] + acc[j][1] + b1);
                *(float2*)(out + (size_t)r0 * HH + c) = o;
            }
            if (r1 < NN) {
                float2 o = make_float2(hC[j][2] + acc[j][2] + b0,
                                       hC[j][3] + acc[j][3] + b1);
                *(float2*)(out + (size_t)r1 * HH + c) = o;
            }
        }
    }
}

// ============================================================================
// Launch — serial (R14 best config).
// ============================================================================
extern "C" void kernel_launch(void* const* d_in, const int* in_sizes, int n_in,
                              void* d_out, int out_size)
{
    const float* x        = (const float*)d_in[0];
    const float* feature1 = (const float*)d_in[1];
    const float* feature2 = (const float*)d_in[2];
    const int *pei, *ei;
    const float* ea;
    if (in_sizes[3] == 2 * EE) {
        pei = (const int*)d_in[3]; ei = (const int*)d_in[4];
        ea  = (const float*)d_in[5];
    } else {
        ea  = (const float*)d_in[3];
        pei = (const int*)d_in[4]; ei = (const int*)d_in[5];
    }
    const float* Wf1a   = (const float*)d_in[6];
    const float* bf1a   = (const float*)d_in[7];
    const float* Wf1b   = (const float*)d_in[8];
    const float* bf1b   = (const float*)d_in[9];
    const float* Wf2a   = (const float*)d_in[10];
    const float* bf2a   = (const float*)d_in[11];
    const float* Wf2b   = (const float*)d_in[12];
    const float* bf2b   = (const float*)d_in[13];
    const float* W1_rel = (const float*)d_in[14];
    const float* b1_rel = (const float*)d_in[15];
    const float* W1_root= (const float*)d_in[16];
    const float* W2_rel = (const float*)d_in[17];
    const float* b2_rel = (const float*)d_in[18];
    const float* W2_root= (const float*)d_in[19];
    const float* epsp   = (const float*)d_in[20];
    const float* Wg1    = (const float*)d_in[21];
    const float* bg1    = (const float*)d_in[22];
    const float* lng    = (const float*)d_in[23];
    const float* lnb    = (const float*)d_in[24];
    const float* Wg2    = (const float*)d_in[25];
    const float* bg2    = (const float*)d_in[26];
    const float* Wc     = (const float*)d_in[27];
    const float* bc     = (const float*)d_in[28];
    float* out = (float*)d_out;

    float* aggbase;
    __half *w1a, *w2a, *w1b, *w2b;
    cudaGetSymbolAddress((void**)&aggbase, g_agg);
    cudaGetSymbolAddress((void**)&w1a, g_W1aT);
    cudaGetSymbolAddress((void**)&w2a, g_W2aT);
    cudaGetSymbolAddress((void**)&w1b, g_W1bT);
    cudaGetSymbolAddress((void**)&w2b, g_W2bT);
    float* agg1 = aggbase;
    float* agg2 = aggbase + (size_t)NN * HH;
    float* agg3 = aggbase + (size_t)2 * NN * HH;

    const int DYN128 = 210432;
    const int DYN32  = 181760;
    cudaFuncSetAttribute(edge_hmma<128>,
                         cudaFuncAttributeMaxDynamicSharedMemorySize, DYN128);
    cudaFuncSetAttribute(edge_hmma<32>,
                         cudaFuncAttributeMaxDynamicSharedMemorySize, DYN32);
    cudaFuncSetAttribute(node_hmma,
                         cudaFuncAttributeMaxDynamicSharedMemorySize, NODE_DYN);

    prep_weights<<<232, 256>>>(Wf1a, Wf1b, Wf2a, Wf2b,
                               W1_rel, W1_root, W2_rel, W2_root, Wc, Wg1, Wg2);

    cudaMemsetAsync(aggbase, 0, sizeof(float) * 3 * NN * HH);

    // 2344 tiles of 256 edges, 8 per CTA -> 293 CTAs (exactly 2 waves)
    edge_hmma<128><<<293, 512, DYN128>>>(feature1, bf1a, bf1b, x, pei, agg1, w1a, w2a);
    edge_hmma<32><<<293, 512, DYN32>>>(feature2, bf2a, bf2b, x, pei, agg2, w1b, w2b);
    gine_scatter<<<EE / 32, 256>>>(x, ea, ei, agg3);

    node_hmma<<<(NN + 127) / 128, 256, NODE_DYN>>>(
        x, b1_rel, b2_rel, bc, epsp, bg1, lng, lnb, bg2, out);
}